// round 9
// baseline (speedup 1.0000x reference)
#include <cuda_runtime.h>
#include <cuda_fp16.h>
#include <math.h>
#include <stdint.h>

#define DD    8
#define NOBJ  64
#define KCH   24
#define QDIM  128
#define OBJF  26
#define HID   256
#define NOUT  28
#define NB    64

// ---------------- PTX helpers (arch-agnostic: sm_80+ instructions only) ----
__device__ __forceinline__ uint32_t smem_u32(const void* p) {
    uint32_t r;
    asm("{ .reg .u64 t; cvta.to.shared.u64 t, %1; cvt.u32.u64 %0, t; }"
        : "=r"(r) : "l"(p));
    return r;
}
#define LDSM4(r0, r1, r2, r3, addr) \
    asm volatile("ldmatrix.sync.aligned.m8n8.x4.shared.b16 {%0,%1,%2,%3}, [%4];" \
                 : "=r"(r0), "=r"(r1), "=r"(r2), "=r"(r3) : "r"(addr))
#define MMA16816(c, a0, a1, a2, a3, b0, b1) \
    asm volatile("mma.sync.aligned.m16n8k16.row.col.f32.f16.f16.f32 " \
                 "{%0,%1,%2,%3}, {%4,%5,%6,%7}, {%8,%9}, {%0,%1,%2,%3};" \
                 : "+f"((c)[0]), "+f"((c)[1]), "+f"((c)[2]), "+f"((c)[3]) \
                 : "r"(a0), "r"(a1), "r"(a2), "r"(a3), "r"(b0), "r"(b1))
#define CP_ASYNC16(dst, src) \
    asm volatile("cp.async.cg.shared.global [%0], [%1], 16;" \
                 :: "r"(dst), "l"(src))
#define CP_COMMIT() asm volatile("cp.async.commit_group;" ::: "memory")
#define CP_WAIT1()  asm volatile("cp.async.wait_group 1;" ::: "memory")
#define CP_WAIT0()  asm volatile("cp.async.wait_group 0;" ::: "memory")

// ---------------- SMEM pool layout (dynamic) ----------------
#define H_ROW_B   528
#define H_PLANE_B (128 * H_ROW_B)          // 67584
#define OFF_H     0
#define OFF_W     H_PLANE_B                // 67584
#define W_ROW_B   272
#define W_PLANE_B (256 * W_ROW_B)          // 69632
#define POOL_B    (OFF_W + 2 * W_PLANE_B)  // 206848 (double buffer)

#define NTHREADS  512

// ---------------- scratch ----------------
__device__ float g_A[NB * NOBJ * HID];
__device__ float g_Bx[NB * NOBJ * HID];
__device__ float g_partial[NB * NOBJ * HID];
__device__ float g_xg[NB * HID];
__device__ __half g_Wt[3 * HID * HID];     // [layer][n][k]  (B = W^T, k-contig)
__device__ float g_fT[2 * HID * HID];      // f1/f2 weights transposed [c][k]

// ============================================================
// prep: factorized g1 terms
// ============================================================
__global__ void prep_kernel(const float* __restrict__ x,
                            const float* __restrict__ qst,
                            const float* __restrict__ g1w,
                            const float* __restrict__ g1b) {
    int b = blockIdx.x;
    __shared__ float xf[NOBJ][OBJF];
    __shared__ float qs[QDIM];
    int tid = threadIdx.x;

    for (int idx = tid; idx < NOBJ * KCH; idx += 256) {
        int k = idx / NOBJ, n = idx % NOBJ;
        xf[n][k] = x[(b * KCH + k) * NOBJ + n];
    }
    if (tid < NOBJ) {
        float a = (float)tid;
        xf[tid][24] = (a / 8.0f - 4.0f) / 4.0f;
        xf[tid][25] = (fmodf(a, 8.0f) - 4.0f) / 4.0f;
    }
    if (tid < QDIM) qs[tid] = qst[b * QDIM + tid];
    __syncthreads();

    int c = tid;
    float wa[OBJF], wb[OBJF];
#pragma unroll
    for (int t = 0; t < OBJF; t++) {
        wa[t] = g1w[t * HID + c];
        wb[t] = g1w[(OBJF + t) * HID + c];
    }
    float bq = g1b[c];
    for (int q = 0; q < QDIM; q++)
        bq += qs[q] * g1w[(2 * OBJF + q) * HID + c];

    for (int n = 0; n < NOBJ; n++) {
        float accA = 0.f, accB = bq;
#pragma unroll
        for (int t = 0; t < OBJF; t++) {
            accA += xf[n][t] * wa[t];
            accB += xf[n][t] * wb[t];
        }
        g_A [(b * NOBJ + n) * HID + c] = accA;
        g_Bx[(b * NOBJ + n) * HID + c] = accB;
    }
}

// ============================================================
// wprep: transpose + fp16 cast of W2/W3/W4; fp32 transpose of f1/f2
// ============================================================
__global__ void wprep_kernel(const float* __restrict__ g2w,
                             const float* __restrict__ g3w,
                             const float* __restrict__ g4w,
                             const float* __restrict__ f1w,
                             const float* __restrict__ f2w) {
    int total = 5 * HID * HID;
    for (int e = blockIdx.x * 256 + threadIdx.x; e < total; e += gridDim.x * 256) {
        int l = e >> 16;
        int rem = e & 65535;
        int n = rem >> 8;
        int k = rem & 255;
        if (l < 3) {
            const float* W = (l == 0) ? g2w : (l == 1) ? g3w : g4w;
            g_Wt[e] = __float2half(W[k * HID + n]);
        } else {
            const float* F = (l == 3) ? f1w : f2w;
            g_fT[(l - 3) * HID * HID + n * HID + k] = F[k * HID + n];
        }
    }
}

// ============================================================
// main tensor kernel: 128 pair-rows / CTA, 3 chained layers via mma.sync
// fp16 activations + fp16 W, fp32 accumulate
// 16 warps (512 thr): warp tile 64x32 = 2 row-groups x 8 col-groups
// ============================================================
struct SharedCtl {
    float bx[2 * HID];
    float bias[3 * HID];
};

__device__ __forceinline__ uint32_t pack_h16x2(float a, float b) {
    __half ha = __float2half(a), hb = __float2half(b);
    return (uint32_t)__half_as_ushort(ha) |
           ((uint32_t)__half_as_ushort(hb) << 16);
}

__global__ __launch_bounds__(NTHREADS, 1)
void pair_mma_kernel(const float* __restrict__ g2b,
                     const float* __restrict__ g3b,
                     const float* __restrict__ g4b) {
    extern __shared__ char pool[];
    __shared__ SharedCtl ctl;

    int tid = threadIdx.x;
    int wid = tid >> 5;
    int lane = tid & 31;
    int g0 = blockIdx.x * 2;           // pair index (b*64+i), even
    int b = g0 >> 6;

    int rg = wid >> 3;                 // row group: rows rg*64 .. +63  (== half)
    int cg = wid & 7;                  // col group: cols cg*32 .. +31
    int row0 = rg * 64;
    int col0 = cg * 32;

    uint32_t pool_u = smem_u32(pool);
    uint32_t H_u = pool_u + OFF_H;
    uint32_t W_u = pool_u + OFF_W;

    // stage biases + Bx rows
    if (tid < 256) {
        ctl.bias[tid]           = g2b[tid];
        ctl.bias[HID + tid]     = g3b[tid];
        ctl.bias[2 * HID + tid] = g4b[tid];
        ctl.bx[tid]       = g_Bx[g0 * HID + tid];
        ctl.bx[HID + tid] = g_Bx[(g0 + 1) * HID + tid];
    }

    // prefetch W slab 0 (layer 0, k=0..127) while we build H1
    {
#pragma unroll
        for (int it = 0; it < 8; it++) {
            int e = tid + it * NTHREADS;       // 0..4095: n, kq
            int n = e >> 4, kq = e & 15;
            const __half* src = g_Wt + n * HID + kq * 8;
            uint32_t dst = W_u + n * W_ROW_B + kq * 16;
            CP_ASYNC16(dst, src);
        }
        CP_COMMIT();
    }
    __syncthreads();   // ctl.bx visible

    // ---- H1 = relu(gA[j] + bx[half]) -> fp16 plane ----
    {
        const float* Ag = g_A + b * NOBJ * HID;
#pragma unroll
        for (int it = 0; it < 32; it++) {
            int idx = tid + it * NTHREADS;     // 0..16383 -> (row, colpair)
            int row = idx >> 7;
            int cp = (idx & 127) * 2;
            int j = row & 63, hf = row >> 6;
            float2 av = *(const float2*)(Ag + j * HID + cp);
            float v0 = fmaxf(av.x + ctl.bx[hf * HID + cp], 0.f);
            float v1 = fmaxf(av.y + ctl.bx[hf * HID + cp + 1], 0.f);
            uint32_t off = (uint32_t)(row * H_ROW_B + cp * 2);
            *(uint32_t*)(pool + OFF_H + off) = pack_h16x2(v0, v1);
        }
    }

    float acc[16][4];   // [at*4 + b8][quad]  (at: 4 m16 tiles, b8: 4 n8 tiles)

    // ---- 6 slab iterations: 3 layers x 2 k-slabs (k=128 each) ----
    for (int t = 0; t < 6; t++) {
        int l = t >> 1, s = t & 1;
        if (s == 0) {
#pragma unroll
            for (int u = 0; u < 16; u++)
#pragma unroll
                for (int q = 0; q < 4; q++) acc[u][q] = 0.f;
        }

        // prefetch next slab into the other buffer
        if (t + 1 < 6) {
            int nl = (t + 1) >> 1, ns = (t + 1) & 1;
            uint32_t wbuf = W_u + ((t + 1) & 1) * W_PLANE_B;
#pragma unroll
            for (int it = 0; it < 8; it++) {
                int e = tid + it * NTHREADS;
                int n = e >> 4, kq = e & 15;
                const __half* src = g_Wt + nl * HID * HID + n * HID + ns * 128 + kq * 8;
                uint32_t dst = wbuf + n * W_ROW_B + kq * 16;
                CP_ASYNC16(dst, src);
            }
            CP_COMMIT();
            CP_WAIT1();
        } else {
            CP_WAIT0();
        }
        __syncthreads();   // current slab ready; prev compute done; H writes visible

        // ---- compute slab (k=128: 8 k16 steps) ----
        uint32_t wsl = W_u + (t & 1) * W_PLANE_B;
#pragma unroll
        for (int kst = 0; kst < 8; kst++) {
            int kglob = s * 128 + kst * 16;
            // A fragments: 4 m16 tiles of this warp's 64 rows
            uint32_t ah[4][4];
#pragma unroll
            for (int at = 0; at < 4; at++) {
                uint32_t a_off = (uint32_t)((row0 + at * 16 + (lane & 15)) * H_ROW_B +
                                            kglob * 2 + (lane >> 4) * 16);
                LDSM4(ah[at][0], ah[at][1], ah[at][2], ah[at][3], H_u + a_off);
            }
            uint32_t b_off = (uint32_t)((lane & 15) * W_ROW_B + kst * 32 +
                                        (lane >> 4) * 16);
            // B fragments: 2 n16 tiles of this warp's 32 cols
#pragma unroll
            for (int bt = 0; bt < 2; bt++) {
                uint32_t bh[4];
                uint32_t bb = wsl + (uint32_t)((col0 + bt * 16) * W_ROW_B) + b_off;
                LDSM4(bh[0], bh[1], bh[2], bh[3], bb);
#pragma unroll
                for (int at = 0; at < 4; at++) {
                    float* a0 = acc[at * 4 + 2 * bt];
                    float* a1 = acc[at * 4 + 2 * bt + 1];
                    MMA16816(a0, ah[at][0], ah[at][1], ah[at][2], ah[at][3], bh[0], bh[2]);
                    MMA16816(a1, ah[at][0], ah[at][1], ah[at][2], ah[at][3], bh[1], bh[3]);
                }
            }
        }
        __syncthreads();   // all warps done reading H / this W buffer

        // ---- layer epilogue (layers 0,1): bias+relu -> fp16 H plane ----
        if (s == 1 && l < 2) {
#pragma unroll
            for (int at = 0; at < 4; at++) {
                int r0 = row0 + at * 16 + (lane >> 2);
                int r1 = r0 + 8;
#pragma unroll
                for (int b8 = 0; b8 < 4; b8++) {
                    float* a = acc[at * 4 + b8];
                    int c0 = col0 + b8 * 8 + (lane & 3) * 2;
                    float2 bias2 = *(const float2*)&ctl.bias[l * HID + c0];
                    float v00 = fmaxf(a[0] + bias2.x, 0.f);
                    float v01 = fmaxf(a[1] + bias2.y, 0.f);
                    float v10 = fmaxf(a[2] + bias2.x, 0.f);
                    float v11 = fmaxf(a[3] + bias2.y, 0.f);
                    uint32_t off0 = (uint32_t)(r0 * H_ROW_B + c0 * 2);
                    uint32_t off1 = (uint32_t)(r1 * H_ROW_B + c0 * 2);
                    *(uint32_t*)(pool + OFF_H + off0) = pack_h16x2(v00, v01);
                    *(uint32_t*)(pool + OFF_H + off1) = pack_h16x2(v10, v11);
                }
            }
        }
    }

    // ---- final layer: bias+relu, reduce this warp's 64 rows (one half),
    //      32 private cols -> direct store to g_partial
    {
#pragma unroll
        for (int b8 = 0; b8 < 4; b8++) {
            int c0 = col0 + b8 * 8 + (lane & 3) * 2;
            float2 bias2 = *(const float2*)&ctl.bias[2 * HID + c0];
            float s0 = 0.f, s1 = 0.f;
#pragma unroll
            for (int at = 0; at < 4; at++) {
                float* a = acc[at * 4 + b8];
                s0 += fmaxf(a[0] + bias2.x, 0.f) + fmaxf(a[2] + bias2.x, 0.f);
                s1 += fmaxf(a[1] + bias2.y, 0.f) + fmaxf(a[3] + bias2.y, 0.f);
            }
#pragma unroll
            for (int off = 4; off < 32; off <<= 1) {
                s0 += __shfl_xor_sync(0xffffffffu, s0, off);
                s1 += __shfl_xor_sync(0xffffffffu, s1, off);
            }
            if (lane < 4) {
                g_partial[(g0 + rg) * HID + c0]     = s0;
                g_partial[(g0 + rg) * HID + c0 + 1] = s1;
            }
        }
    }
}

// ============================================================
// deterministic reduce over i
// ============================================================
__global__ void reduce_kernel() {
    int b = blockIdx.x;
    int c = threadIdx.x;
    float s = 0.f;
    for (int i = 0; i < NOBJ; i++) s += g_partial[(b * NOBJ + i) * HID + c];
    g_xg[b * HID + c] = s;
}

// ============================================================
// f-MLP + log_softmax (transposed weights, float4 k-loops)
// ============================================================
__global__ void f_kernel(const float* __restrict__ f1b,
                         const float* __restrict__ f2b,
                         const float* __restrict__ f3w, const float* __restrict__ f3b,
                         float* __restrict__ out) {
    int b = blockIdx.x;
    int tid = threadIdx.x;
    __shared__ float h0[HID], h1[HID], h2[HID], lg[NOUT], red[2];

    h0[tid] = g_xg[b * HID + tid];
    __syncthreads();

    {
        float a = f1b[tid];
        const float4* w4 = (const float4*)(g_fT + tid * HID);
        const float4* h4 = (const float4*)h0;
#pragma unroll 8
        for (int k = 0; k < HID / 4; k++) {
            float4 w = w4[k], h = h4[k];
            a += w.x * h.x + w.y * h.y + w.z * h.z + w.w * h.w;
        }
        h1[tid] = fmaxf(a, 0.f);
    }
    __syncthreads();

    {
        float a = f2b[tid];
        const float4* w4 = (const float4*)(g_fT + HID * HID + tid * HID);
        const float4* h4 = (const float4*)h1;
#pragma unroll 8
        for (int k = 0; k < HID / 4; k++) {
            float4 w = w4[k], h = h4[k];
            a += w.x * h.x + w.y * h.y + w.z * h.z + w.w * h.w;
        }
        h2[tid] = fmaxf(a, 0.f);
    }
    __syncthreads();

    if (tid < NOUT) {
        float a = f3b[tid];
        for (int k = 0; k < HID; k++) a += h2[k] * f3w[k * NOUT + tid];
        lg[tid] = a;
    }
    __syncthreads();

    if (tid == 0) {
        float m = lg[0];
        for (int c = 1; c < NOUT; c++) m = fmaxf(m, lg[c]);
        float se = 0.f;
        for (int c = 0; c < NOUT; c++) se += expf(lg[c] - m);
        red[0] = m;
        red[1] = logf(se);
    }
    __syncthreads();

    if (tid < NOUT) out[b * NOUT + tid] = lg[tid] - red[0] - red[1];
}

// ============================================================
extern "C" void kernel_launch(void* const* d_in, const int* in_sizes, int n_in,
                              void* d_out, int out_size) {
    const float* x   = (const float*)d_in[0];
    const float* qst = (const float*)d_in[1];
    const float* g1w = (const float*)d_in[2];
    const float* g1b = (const float*)d_in[3];
    const float* g2w = (const float*)d_in[4];
    const float* g2b = (const float*)d_in[5];
    const float* g3w = (const float*)d_in[6];
    const float* g3b = (const float*)d_in[7];
    const float* g4w = (const float*)d_in[8];
    const float* g4b = (const float*)d_in[9];
    const float* f1w = (const float*)d_in[10];
    const float* f1b = (const float*)d_in[11];
    const float* f2w = (const float*)d_in[12];
    const float* f2b = (const float*)d_in[13];
    const float* f3w = (const float*)d_in[14];
    const float* f3b = (const float*)d_in[15];
    float* out = (float*)d_out;

    cudaFuncSetAttribute(pair_mma_kernel,
                         cudaFuncAttributeMaxDynamicSharedMemorySize, POOL_B);

    prep_kernel<<<NB, 256>>>(x, qst, g1w, g1b);
    wprep_kernel<<<148, 256>>>(g2w, g3w, g4w, f1w, f2w);
    pair_mma_kernel<<<(NB * NOBJ) / 2, NTHREADS, POOL_B>>>(g2b, g3b, g4b);
    reduce_kernel<<<NB, 256>>>();
    f_kernel<<<NB, 256>>>(f1b, f2b, f3w, f3b, out);
}

// round 10
// speedup vs baseline: 1.0138x; 1.0138x over previous
#include <cuda_runtime.h>
#include <cuda_fp16.h>
#include <math.h>
#include <stdint.h>

#define DD    8
#define NOBJ  64
#define KCH   24
#define QDIM  128
#define OBJF  26
#define HID   256
#define NOUT  28
#define NB    64

// ---------------- PTX helpers (arch-agnostic: sm_80+ instructions only) ----
__device__ __forceinline__ uint32_t smem_u32(const void* p) {
    uint32_t r;
    asm("{ .reg .u64 t; cvta.to.shared.u64 t, %1; cvt.u32.u64 %0, t; }"
        : "=r"(r) : "l"(p));
    return r;
}
#define LDSM4(r0, r1, r2, r3, addr) \
    asm volatile("ldmatrix.sync.aligned.m8n8.x4.shared.b16 {%0,%1,%2,%3}, [%4];" \
                 : "=r"(r0), "=r"(r1), "=r"(r2), "=r"(r3) : "r"(addr))
#define MMA16816(c, a0, a1, a2, a3, b0, b1) \
    asm volatile("mma.sync.aligned.m16n8k16.row.col.f32.f16.f16.f32 " \
                 "{%0,%1,%2,%3}, {%4,%5,%6,%7}, {%8,%9}, {%0,%1,%2,%3};" \
                 : "+f"((c)[0]), "+f"((c)[1]), "+f"((c)[2]), "+f"((c)[3]) \
                 : "r"(a0), "r"(a1), "r"(a2), "r"(a3), "r"(b0), "r"(b1))
#define CP_ASYNC16(dst, src) \
    asm volatile("cp.async.cg.shared.global [%0], [%1], 16;" \
                 :: "r"(dst), "l"(src))
#define CP_COMMIT() asm volatile("cp.async.commit_group;" ::: "memory")
#define CP_WAIT1()  asm volatile("cp.async.wait_group 1;" ::: "memory")
#define CP_WAIT0()  asm volatile("cp.async.wait_group 0;" ::: "memory")

// ---------------- SMEM pool layout (dynamic) ----------------
#define H_ROW_B   528
#define H_PLANE_B (128 * H_ROW_B)          // 67584
#define OFF_H     0
#define OFF_W     H_PLANE_B                // 67584
#define W_ROW_B   272
#define W_PLANE_B (256 * W_ROW_B)          // 69632
#define POOL_B    (OFF_W + 2 * W_PLANE_B)  // 206848 (double buffer)

// ---------------- scratch ----------------
__device__ float g_A[NB * NOBJ * HID];
__device__ float g_Bx[NB * NOBJ * HID];
__device__ float g_partial[NB * NOBJ * HID];
__device__ __half g_Wt[3 * HID * HID];     // [layer][n][k]  (B = W^T, k-contig)
__device__ float g_fT[2 * HID * HID];      // f1/f2 weights transposed [c][k]

// ============================================================
// combined prep: blocks 0..63 -> g1 factorization; 64..211 -> W transposes
// ============================================================
__global__ void prep_kernel(const float* __restrict__ x,
                            const float* __restrict__ qst,
                            const float* __restrict__ g1w,
                            const float* __restrict__ g1b,
                            const float* __restrict__ g2w,
                            const float* __restrict__ g3w,
                            const float* __restrict__ g4w,
                            const float* __restrict__ f1w,
                            const float* __restrict__ f2w) {
    int tid = threadIdx.x;
    if (blockIdx.x >= NB) {
        // ---- weight transposes ----
        int blk = blockIdx.x - NB;          // 0..147
        int total = 5 * HID * HID;
        for (int e = blk * 256 + tid; e < total; e += 148 * 256) {
            int l = e >> 16;
            int rem = e & 65535;
            int n = rem >> 8;
            int k = rem & 255;
            if (l < 3) {
                const float* W = (l == 0) ? g2w : (l == 1) ? g3w : g4w;
                g_Wt[e] = __float2half(W[k * HID + n]);
            } else {
                const float* F = (l == 3) ? f1w : f2w;
                g_fT[(l - 3) * HID * HID + n * HID + k] = F[k * HID + n];
            }
        }
        return;
    }

    int b = blockIdx.x;
    __shared__ float xf[NOBJ][OBJF];
    __shared__ float qs[QDIM];

    for (int idx = tid; idx < NOBJ * KCH; idx += 256) {
        int k = idx / NOBJ, n = idx % NOBJ;
        xf[n][k] = x[(b * KCH + k) * NOBJ + n];
    }
    if (tid < NOBJ) {
        float a = (float)tid;
        xf[tid][24] = (a / 8.0f - 4.0f) / 4.0f;
        xf[tid][25] = (fmodf(a, 8.0f) - 4.0f) / 4.0f;
    }
    if (tid < QDIM) qs[tid] = qst[b * QDIM + tid];
    __syncthreads();

    int c = tid;
    float wa[OBJF], wb[OBJF];
#pragma unroll
    for (int t = 0; t < OBJF; t++) {
        wa[t] = g1w[t * HID + c];
        wb[t] = g1w[(OBJF + t) * HID + c];
    }
    float bq = g1b[c];
    for (int q = 0; q < QDIM; q++)
        bq += qs[q] * g1w[(2 * OBJF + q) * HID + c];

    for (int n = 0; n < NOBJ; n++) {
        float accA = 0.f, accB = bq;
#pragma unroll
        for (int t = 0; t < OBJF; t++) {
            accA += xf[n][t] * wa[t];
            accB += xf[n][t] * wb[t];
        }
        g_A [(b * NOBJ + n) * HID + c] = accA;
        g_Bx[(b * NOBJ + n) * HID + c] = accB;
    }
}

// ============================================================
// main tensor kernel (R7 config): 128 pair-rows / CTA, 3 chained layers
// fp16 activations + fp16 W, fp32 accumulate
// 8 warps (256 thr): warp tile 64x64 = 2 row-groups x 4 col-groups
// ============================================================
struct SharedCtl {
    float bx[2 * HID];
    float bias[3 * HID];
};

__device__ __forceinline__ uint32_t pack_h16x2(float a, float b) {
    __half ha = __float2half(a), hb = __float2half(b);
    return (uint32_t)__half_as_ushort(ha) |
           ((uint32_t)__half_as_ushort(hb) << 16);
}

__global__ __launch_bounds__(256, 1)
void pair_mma_kernel(const float* __restrict__ g2b,
                     const float* __restrict__ g3b,
                     const float* __restrict__ g4b) {
    extern __shared__ char pool[];
    __shared__ SharedCtl ctl;

    int tid = threadIdx.x;
    int wid = tid >> 5;
    int lane = tid & 31;
    int g0 = blockIdx.x * 2;           // pair index (b*64+i), even
    int b = g0 >> 6;

    int rg = wid >> 2;                 // row group: rows rg*64 .. +63  (== half)
    int cg = wid & 3;                  // col group: cols cg*64 .. +63
    int row0 = rg * 64;
    int col0 = cg * 64;

    uint32_t pool_u = smem_u32(pool);
    uint32_t H_u = pool_u + OFF_H;
    uint32_t W_u = pool_u + OFF_W;

    // stage biases + Bx rows
    ctl.bias[tid]           = g2b[tid];
    ctl.bias[HID + tid]     = g3b[tid];
    ctl.bias[2 * HID + tid] = g4b[tid];
    ctl.bx[tid]       = g_Bx[g0 * HID + tid];
    ctl.bx[HID + tid] = g_Bx[(g0 + 1) * HID + tid];

    // prefetch W slab 0 (layer 0, k=0..127) while we build H1
    {
#pragma unroll
        for (int it = 0; it < 16; it++) {
            int e = tid + it * 256;            // 0..4095: n, kq
            int n = e >> 4, kq = e & 15;
            const __half* src = g_Wt + n * HID + kq * 8;
            uint32_t dst = W_u + n * W_ROW_B + kq * 16;
            CP_ASYNC16(dst, src);
        }
        CP_COMMIT();
    }
    __syncthreads();   // ctl.bx visible

    // ---- H1 = relu(gA[j] + bx[half]) -> fp16 plane ----
    {
        const float* Ag = g_A + b * NOBJ * HID;
#pragma unroll
        for (int it = 0; it < 64; it++) {
            int idx = tid + it * 256;          // 0..16383 -> (row, colpair)
            int row = idx >> 7;
            int cp = (idx & 127) * 2;
            int j = row & 63, hf = row >> 6;
            float2 av = *(const float2*)(Ag + j * HID + cp);
            float v0 = fmaxf(av.x + ctl.bx[hf * HID + cp], 0.f);
            float v1 = fmaxf(av.y + ctl.bx[hf * HID + cp + 1], 0.f);
            uint32_t off = (uint32_t)(row * H_ROW_B + cp * 2);
            *(uint32_t*)(pool + OFF_H + off) = pack_h16x2(v0, v1);
        }
    }

    float acc[32][4];   // [at*8 + b8][quad]  (at: 4 m16 tiles, b8: 8 n8 tiles)

    // ---- 6 slab iterations: 3 layers x 2 k-slabs (k=128 each) ----
    for (int t = 0; t < 6; t++) {
        int l = t >> 1, s = t & 1;
        if (s == 0) {
#pragma unroll
            for (int u = 0; u < 32; u++)
#pragma unroll
                for (int q = 0; q < 4; q++) acc[u][q] = 0.f;
        }

        // prefetch next slab into the other buffer
        if (t + 1 < 6) {
            int nl = (t + 1) >> 1, ns = (t + 1) & 1;
            uint32_t wbuf = W_u + ((t + 1) & 1) * W_PLANE_B;
#pragma unroll
            for (int it = 0; it < 16; it++) {
                int e = tid + it * 256;
                int n = e >> 4, kq = e & 15;
                const __half* src = g_Wt + nl * HID * HID + n * HID + ns * 128 + kq * 8;
                uint32_t dst = wbuf + n * W_ROW_B + kq * 16;
                CP_ASYNC16(dst, src);
            }
            CP_COMMIT();
            CP_WAIT1();
        } else {
            CP_WAIT0();
        }
        __syncthreads();   // current slab ready; prev compute done; H writes visible

        // ---- compute slab (k=128: 8 k16 steps) ----
        uint32_t wsl = W_u + (t & 1) * W_PLANE_B;
#pragma unroll
        for (int kst = 0; kst < 8; kst++) {
            int kglob = s * 128 + kst * 16;
            // A fragments: 4 m16 tiles of this warp's 64 rows
            uint32_t ah[4][4];
#pragma unroll
            for (int at = 0; at < 4; at++) {
                uint32_t a_off = (uint32_t)((row0 + at * 16 + (lane & 15)) * H_ROW_B +
                                            kglob * 2 + (lane >> 4) * 16);
                LDSM4(ah[at][0], ah[at][1], ah[at][2], ah[at][3], H_u + a_off);
            }
            uint32_t b_off = (uint32_t)((lane & 15) * W_ROW_B + kst * 32 +
                                        (lane >> 4) * 16);
            // B fragments: 4 n16 tiles of this warp's 64 cols
#pragma unroll
            for (int bt = 0; bt < 4; bt++) {
                uint32_t bh[4];
                uint32_t bb = wsl + (uint32_t)((col0 + bt * 16) * W_ROW_B) + b_off;
                LDSM4(bh[0], bh[1], bh[2], bh[3], bb);
#pragma unroll
                for (int at = 0; at < 4; at++) {
                    float* a0 = acc[at * 8 + 2 * bt];
                    float* a1 = acc[at * 8 + 2 * bt + 1];
                    MMA16816(a0, ah[at][0], ah[at][1], ah[at][2], ah[at][3], bh[0], bh[2]);
                    MMA16816(a1, ah[at][0], ah[at][1], ah[at][2], ah[at][3], bh[1], bh[3]);
                }
            }
        }
        __syncthreads();   // all warps done reading H / this W buffer

        // ---- layer epilogue (layers 0,1): bias+relu -> fp16 H plane ----
        if (s == 1 && l < 2) {
#pragma unroll
            for (int at = 0; at < 4; at++) {
                int r0 = row0 + at * 16 + (lane >> 2);
                int r1 = r0 + 8;
#pragma unroll
                for (int b8 = 0; b8 < 8; b8++) {
                    float* a = acc[at * 8 + b8];
                    int c0 = col0 + b8 * 8 + (lane & 3) * 2;
                    float2 bias2 = *(const float2*)&ctl.bias[l * HID + c0];
                    float v00 = fmaxf(a[0] + bias2.x, 0.f);
                    float v01 = fmaxf(a[1] + bias2.y, 0.f);
                    float v10 = fmaxf(a[2] + bias2.x, 0.f);
                    float v11 = fmaxf(a[3] + bias2.y, 0.f);
                    uint32_t off0 = (uint32_t)(r0 * H_ROW_B + c0 * 2);
                    uint32_t off1 = (uint32_t)(r1 * H_ROW_B + c0 * 2);
                    *(uint32_t*)(pool + OFF_H + off0) = pack_h16x2(v00, v01);
                    *(uint32_t*)(pool + OFF_H + off1) = pack_h16x2(v10, v11);
                }
            }
        }
    }

    // ---- final layer: bias+relu, reduce this warp's 64 rows (one half),
    //      64 private cols -> direct store to g_partial
    {
#pragma unroll
        for (int b8 = 0; b8 < 8; b8++) {
            int c0 = col0 + b8 * 8 + (lane & 3) * 2;
            float2 bias2 = *(const float2*)&ctl.bias[2 * HID + c0];
            float s0 = 0.f, s1 = 0.f;
#pragma unroll
            for (int at = 0; at < 4; at++) {
                float* a = acc[at * 8 + b8];
                s0 += fmaxf(a[0] + bias2.x, 0.f) + fmaxf(a[2] + bias2.x, 0.f);
                s1 += fmaxf(a[1] + bias2.y, 0.f) + fmaxf(a[3] + bias2.y, 0.f);
            }
#pragma unroll
            for (int off = 4; off < 32; off <<= 1) {
                s0 += __shfl_xor_sync(0xffffffffu, s0, off);
                s1 += __shfl_xor_sync(0xffffffffu, s1, off);
            }
            if (lane < 4) {
                g_partial[(g0 + rg) * HID + c0]     = s0;
                g_partial[(g0 + rg) * HID + c0 + 1] = s1;
            }
        }
    }
}

// ============================================================
// f-MLP + log_softmax, with fused i-reduction (transposed f weights)
// ============================================================
__global__ void f_kernel(const float* __restrict__ f1b,
                         const float* __restrict__ f2b,
                         const float* __restrict__ f3w, const float* __restrict__ f3b,
                         float* __restrict__ out) {
    int b = blockIdx.x;
    int tid = threadIdx.x;
    __shared__ float h0[HID], h1[HID], h2[HID], lg[NOUT], red[2];

    // fused deterministic reduce over i
    {
        float s = 0.f;
        const float* p = g_partial + b * NOBJ * HID + tid;
        for (int i = 0; i < NOBJ; i++) s += p[i * HID];
        h0[tid] = s;
    }
    __syncthreads();

    {
        float a = f1b[tid];
        const float4* w4 = (const float4*)(g_fT + tid * HID);
        const float4* h4 = (const float4*)h0;
#pragma unroll 8
        for (int k = 0; k < HID / 4; k++) {
            float4 w = w4[k], h = h4[k];
            a += w.x * h.x + w.y * h.y + w.z * h.z + w.w * h.w;
        }
        h1[tid] = fmaxf(a, 0.f);
    }
    __syncthreads();

    {
        float a = f2b[tid];
        const float4* w4 = (const float4*)(g_fT + HID * HID + tid * HID);
        const float4* h4 = (const float4*)h1;
#pragma unroll 8
        for (int k = 0; k < HID / 4; k++) {
            float4 w = w4[k], h = h4[k];
            a += w.x * h.x + w.y * h.y + w.z * h.z + w.w * h.w;
        }
        h2[tid] = fmaxf(a, 0.f);
    }
    __syncthreads();

    if (tid < NOUT) {
        float a = f3b[tid];
        for (int k = 0; k < HID; k++) a += h2[k] * f3w[k * NOUT + tid];
        lg[tid] = a;
    }
    __syncthreads();

    if (tid == 0) {
        float m = lg[0];
        for (int c = 1; c < NOUT; c++) m = fmaxf(m, lg[c]);
        float se = 0.f;
        for (int c = 0; c < NOUT; c++) se += expf(lg[c] - m);
        red[0] = m;
        red[1] = logf(se);
    }
    __syncthreads();

    if (tid < NOUT) out[b * NOUT + tid] = lg[tid] - red[0] - red[1];
}

// ============================================================
extern "C" void kernel_launch(void* const* d_in, const int* in_sizes, int n_in,
                              void* d_out, int out_size) {
    const float* x   = (const float*)d_in[0];
    const float* qst = (const float*)d_in[1];
    const float* g1w = (const float*)d_in[2];
    const float* g1b = (const float*)d_in[3];
    const float* g2w = (const float*)d_in[4];
    const float* g2b = (const float*)d_in[5];
    const float* g3w = (const float*)d_in[6];
    const float* g3b = (const float*)d_in[7];
    const float* g4w = (const float*)d_in[8];
    const float* g4b = (const float*)d_in[9];
    const float* f1w = (const float*)d_in[10];
    const float* f1b = (const float*)d_in[11];
    const float* f2w = (const float*)d_in[12];
    const float* f2b = (const float*)d_in[13];
    const float* f3w = (const float*)d_in[14];
    const float* f3b = (const float*)d_in[15];
    float* out = (float*)d_out;

    cudaFuncSetAttribute(pair_mma_kernel,
                         cudaFuncAttributeMaxDynamicSharedMemorySize, POOL_B);

    prep_kernel<<<NB + 148, 256>>>(x, qst, g1w, g1b, g2w, g3w, g4w, f1w, f2w);
    pair_mma_kernel<<<(NB * NOBJ) / 2, 256, POOL_B>>>(g2b, g3b, g4b);
    f_kernel<<<NB, 256>>>(f1b, f2b, f3w, f3b, out);
}

// round 11
// speedup vs baseline: 1.0206x; 1.0067x over previous
#include <cuda_runtime.h>
#include <cuda_fp16.h>
#include <math.h>
#include <stdint.h>

#define DD    8
#define NOBJ  64
#define KCH   24
#define QDIM  128
#define OBJF  26
#define HID   256
#define NOUT  28
#define NB    64

// ---------------- PTX helpers (arch-agnostic: sm_80+ instructions only) ----
__device__ __forceinline__ uint32_t smem_u32(const void* p) {
    uint32_t r;
    asm("{ .reg .u64 t; cvta.to.shared.u64 t, %1; cvt.u32.u64 %0, t; }"
        : "=r"(r) : "l"(p));
    return r;
}
#define LDSM4(r0, r1, r2, r3, addr) \
    asm volatile("ldmatrix.sync.aligned.m8n8.x4.shared.b16 {%0,%1,%2,%3}, [%4];" \
                 : "=r"(r0), "=r"(r1), "=r"(r2), "=r"(r3) : "r"(addr))
#define MMA16816(c, a0, a1, a2, a3, b0, b1) \
    asm volatile("mma.sync.aligned.m16n8k16.row.col.f32.f16.f16.f32 " \
                 "{%0,%1,%2,%3}, {%4,%5,%6,%7}, {%8,%9}, {%0,%1,%2,%3};" \
                 : "+f"((c)[0]), "+f"((c)[1]), "+f"((c)[2]), "+f"((c)[3]) \
                 : "r"(a0), "r"(a1), "r"(a2), "r"(a3), "r"(b0), "r"(b1))
#define CP_ASYNC16(dst, src) \
    asm volatile("cp.async.cg.shared.global [%0], [%1], 16;" \
                 :: "r"(dst), "l"(src))
#define CP_COMMIT() asm volatile("cp.async.commit_group;" ::: "memory")
#define CP_WAIT1()  asm volatile("cp.async.wait_group 1;" ::: "memory")
#define CP_WAIT0()  asm volatile("cp.async.wait_group 0;" ::: "memory")

// ---------------- SMEM pool layout (dynamic) ----------------
#define H_ROW_B   528
#define H_PLANE_B (128 * H_ROW_B)          // 67584
#define OFF_H     0
#define OFF_W     H_PLANE_B                // 67584
#define W_ROW_B   272
#define W_PLANE_B (256 * W_ROW_B)          // 69632
#define POOL_B    (OFF_W + 2 * W_PLANE_B)  // 206848 (double buffer)

// ---------------- scratch ----------------
__device__ float g_A[NB * NOBJ * HID];
__device__ float g_Bx[NB * NOBJ * HID];
__device__ float g_partial[NB * NOBJ * HID];
__device__ __half g_Wt[3 * HID * HID];     // [layer][n][k]  (B = W^T, k-contig)
__device__ float g_fT[2 * HID * HID];      // f1/f2 weights transposed [c][k]

// ============================================================
// combined prep:
//   blocks 0..63       -> g1 factorization (per batch)
//   blocks 64..383     -> coalesced 32x32 tiled transposes of W2/W3/W4/f1/f2
// ============================================================
__global__ void prep_kernel(const float* __restrict__ x,
                            const float* __restrict__ qst,
                            const float* __restrict__ g1w,
                            const float* __restrict__ g1b,
                            const float* __restrict__ g2w,
                            const float* __restrict__ g3w,
                            const float* __restrict__ g4w,
                            const float* __restrict__ f1w,
                            const float* __restrict__ f2w) {
    int tid = threadIdx.x;
    if (blockIdx.x >= NB) {
        // ---- tiled transpose: src [k][n] row-major -> dst [n][k] ----
        __shared__ float tile[32][33];
        int tt = blockIdx.x - NB;          // 0..319
        int l = tt >> 6;                   // 0..4
        int tile_id = tt & 63;
        int tr = tile_id >> 3;             // k-block
        int tc = tile_id & 7;              // n-block
        const float* src = (l == 0) ? g2w : (l == 1) ? g3w : (l == 2) ? g4w
                          : (l == 3) ? f1w : f2w;
        int kb = tr * 32, nb = tc * 32;
        int lr = tid >> 5, lc = tid & 31;  // 8 rows/pass, 32 cols
#pragma unroll
        for (int p = 0; p < 4; p++) {
            int k = kb + lr + p * 8;
            tile[lr + p * 8][lc] = src[k * HID + nb + lc];
        }
        __syncthreads();
        if (l < 3) {
            __half* dst = g_Wt + l * HID * HID;
#pragma unroll
            for (int p = 0; p < 4; p++) {
                int n = nb + lr + p * 8;
                dst[n * HID + kb + lc] = __float2half(tile[lc][lr + p * 8]);
            }
        } else {
            float* dst = g_fT + (l - 3) * HID * HID;
#pragma unroll
            for (int p = 0; p < 4; p++) {
                int n = nb + lr + p * 8;
                dst[n * HID + kb + lc] = tile[lc][lr + p * 8];
            }
        }
        return;
    }

    int b = blockIdx.x;
    __shared__ float xf[NOBJ][OBJF];
    __shared__ float qs[QDIM];

    for (int idx = tid; idx < NOBJ * KCH; idx += 256) {
        int k = idx / NOBJ, n = idx % NOBJ;
        xf[n][k] = x[(b * KCH + k) * NOBJ + n];
    }
    if (tid < NOBJ) {
        float a = (float)tid;
        xf[tid][24] = (a / 8.0f - 4.0f) / 4.0f;
        xf[tid][25] = (fmodf(a, 8.0f) - 4.0f) / 4.0f;
    }
    if (tid < QDIM) qs[tid] = qst[b * QDIM + tid];
    __syncthreads();

    int c = tid;
    float wa[OBJF], wb[OBJF];
#pragma unroll
    for (int t = 0; t < OBJF; t++) {
        wa[t] = g1w[t * HID + c];
        wb[t] = g1w[(OBJF + t) * HID + c];
    }
    float bq = g1b[c];
    for (int q = 0; q < QDIM; q++)
        bq += qs[q] * g1w[(2 * OBJF + q) * HID + c];

    for (int n = 0; n < NOBJ; n++) {
        float accA = 0.f, accB = bq;
#pragma unroll
        for (int t = 0; t < OBJF; t++) {
            accA += xf[n][t] * wa[t];
            accB += xf[n][t] * wb[t];
        }
        g_A [(b * NOBJ + n) * HID + c] = accA;
        g_Bx[(b * NOBJ + n) * HID + c] = accB;
    }
}

// ============================================================
// main tensor kernel (R7 config): 128 pair-rows / CTA, 3 chained layers
// fp16 activations + fp16 W, fp32 accumulate
// 8 warps (256 thr): warp tile 64x64 = 2 row-groups x 4 col-groups
// ============================================================
struct SharedCtl {
    float bx[2 * HID];
    float bias[3 * HID];
};

__device__ __forceinline__ uint32_t pack_h16x2(float a, float b) {
    __half ha = __float2half(a), hb = __float2half(b);
    return (uint32_t)__half_as_ushort(ha) |
           ((uint32_t)__half_as_ushort(hb) << 16);
}

__global__ __launch_bounds__(256, 1)
void pair_mma_kernel(const float* __restrict__ g2b,
                     const float* __restrict__ g3b,
                     const float* __restrict__ g4b) {
    extern __shared__ char pool[];
    __shared__ SharedCtl ctl;

    int tid = threadIdx.x;
    int wid = tid >> 5;
    int lane = tid & 31;
    int g0 = blockIdx.x * 2;           // pair index (b*64+i), even
    int b = g0 >> 6;

    int rg = wid >> 2;                 // row group: rows rg*64 .. +63  (== half)
    int cg = wid & 3;                  // col group: cols cg*64 .. +63
    int row0 = rg * 64;
    int col0 = cg * 64;

    uint32_t pool_u = smem_u32(pool);
    uint32_t H_u = pool_u + OFF_H;
    uint32_t W_u = pool_u + OFF_W;

    // stage biases + Bx rows
    ctl.bias[tid]           = g2b[tid];
    ctl.bias[HID + tid]     = g3b[tid];
    ctl.bias[2 * HID + tid] = g4b[tid];
    ctl.bx[tid]       = g_Bx[g0 * HID + tid];
    ctl.bx[HID + tid] = g_Bx[(g0 + 1) * HID + tid];

    // prefetch W slab 0 (layer 0, k=0..127) while we build H1
    {
#pragma unroll
        for (int it = 0; it < 16; it++) {
            int e = tid + it * 256;            // 0..4095: n, kq
            int n = e >> 4, kq = e & 15;
            const __half* src = g_Wt + n * HID + kq * 8;
            uint32_t dst = W_u + n * W_ROW_B + kq * 16;
            CP_ASYNC16(dst, src);
        }
        CP_COMMIT();
    }
    __syncthreads();   // ctl.bx visible

    // ---- H1 = relu(gA[j] + bx[half]) -> fp16 plane ----
    {
        const float* Ag = g_A + b * NOBJ * HID;
#pragma unroll
        for (int it = 0; it < 64; it++) {
            int idx = tid + it * 256;          // 0..16383 -> (row, colpair)
            int row = idx >> 7;
            int cp = (idx & 127) * 2;
            int j = row & 63, hf = row >> 6;
            float2 av = *(const float2*)(Ag + j * HID + cp);
            float v0 = fmaxf(av.x + ctl.bx[hf * HID + cp], 0.f);
            float v1 = fmaxf(av.y + ctl.bx[hf * HID + cp + 1], 0.f);
            uint32_t off = (uint32_t)(row * H_ROW_B + cp * 2);
            *(uint32_t*)(pool + OFF_H + off) = pack_h16x2(v0, v1);
        }
    }

    float acc[32][4];   // [at*8 + b8][quad]  (at: 4 m16 tiles, b8: 8 n8 tiles)

    // ---- 6 slab iterations: 3 layers x 2 k-slabs (k=128 each) ----
    for (int t = 0; t < 6; t++) {
        int l = t >> 1, s = t & 1;
        if (s == 0) {
#pragma unroll
            for (int u = 0; u < 32; u++)
#pragma unroll
                for (int q = 0; q < 4; q++) acc[u][q] = 0.f;
        }

        // prefetch next slab into the other buffer
        if (t + 1 < 6) {
            int nl = (t + 1) >> 1, ns = (t + 1) & 1;
            uint32_t wbuf = W_u + ((t + 1) & 1) * W_PLANE_B;
#pragma unroll
            for (int it = 0; it < 16; it++) {
                int e = tid + it * 256;
                int n = e >> 4, kq = e & 15;
                const __half* src = g_Wt + nl * HID * HID + n * HID + ns * 128 + kq * 8;
                uint32_t dst = wbuf + n * W_ROW_B + kq * 16;
                CP_ASYNC16(dst, src);
            }
            CP_COMMIT();
            CP_WAIT1();
        } else {
            CP_WAIT0();
        }
        __syncthreads();   // current slab ready; prev compute done; H writes visible

        // ---- compute slab (k=128: 8 k16 steps) ----
        uint32_t wsl = W_u + (t & 1) * W_PLANE_B;
#pragma unroll
        for (int kst = 0; kst < 8; kst++) {
            int kglob = s * 128 + kst * 16;
            // A fragments: 4 m16 tiles of this warp's 64 rows
            uint32_t ah[4][4];
#pragma unroll
            for (int at = 0; at < 4; at++) {
                uint32_t a_off = (uint32_t)((row0 + at * 16 + (lane & 15)) * H_ROW_B +
                                            kglob * 2 + (lane >> 4) * 16);
                LDSM4(ah[at][0], ah[at][1], ah[at][2], ah[at][3], H_u + a_off);
            }
            uint32_t b_off = (uint32_t)((lane & 15) * W_ROW_B + kst * 32 +
                                        (lane >> 4) * 16);
            // B fragments: 4 n16 tiles of this warp's 64 cols
#pragma unroll
            for (int bt = 0; bt < 4; bt++) {
                uint32_t bh[4];
                uint32_t bb = wsl + (uint32_t)((col0 + bt * 16) * W_ROW_B) + b_off;
                LDSM4(bh[0], bh[1], bh[2], bh[3], bb);
#pragma unroll
                for (int at = 0; at < 4; at++) {
                    float* a0 = acc[at * 8 + 2 * bt];
                    float* a1 = acc[at * 8 + 2 * bt + 1];
                    MMA16816(a0, ah[at][0], ah[at][1], ah[at][2], ah[at][3], bh[0], bh[2]);
                    MMA16816(a1, ah[at][0], ah[at][1], ah[at][2], ah[at][3], bh[1], bh[3]);
                }
            }
        }
        __syncthreads();   // all warps done reading H / this W buffer

        // ---- layer epilogue (layers 0,1): bias+relu -> fp16 H plane ----
        if (s == 1 && l < 2) {
#pragma unroll
            for (int at = 0; at < 4; at++) {
                int r0 = row0 + at * 16 + (lane >> 2);
                int r1 = r0 + 8;
#pragma unroll
                for (int b8 = 0; b8 < 8; b8++) {
                    float* a = acc[at * 8 + b8];
                    int c0 = col0 + b8 * 8 + (lane & 3) * 2;
                    float2 bias2 = *(const float2*)&ctl.bias[l * HID + c0];
                    float v00 = fmaxf(a[0] + bias2.x, 0.f);
                    float v01 = fmaxf(a[1] + bias2.y, 0.f);
                    float v10 = fmaxf(a[2] + bias2.x, 0.f);
                    float v11 = fmaxf(a[3] + bias2.y, 0.f);
                    uint32_t off0 = (uint32_t)(r0 * H_ROW_B + c0 * 2);
                    uint32_t off1 = (uint32_t)(r1 * H_ROW_B + c0 * 2);
                    *(uint32_t*)(pool + OFF_H + off0) = pack_h16x2(v00, v01);
                    *(uint32_t*)(pool + OFF_H + off1) = pack_h16x2(v10, v11);
                }
            }
        }
    }

    // ---- final layer: bias+relu, reduce this warp's 64 rows (one half),
    //      64 private cols -> direct store to g_partial
    {
#pragma unroll
        for (int b8 = 0; b8 < 8; b8++) {
            int c0 = col0 + b8 * 8 + (lane & 3) * 2;
            float2 bias2 = *(const float2*)&ctl.bias[2 * HID + c0];
            float s0 = 0.f, s1 = 0.f;
#pragma unroll
            for (int at = 0; at < 4; at++) {
                float* a = acc[at * 8 + b8];
                s0 += fmaxf(a[0] + bias2.x, 0.f) + fmaxf(a[2] + bias2.x, 0.f);
                s1 += fmaxf(a[1] + bias2.y, 0.f) + fmaxf(a[3] + bias2.y, 0.f);
            }
#pragma unroll
            for (int off = 4; off < 32; off <<= 1) {
                s0 += __shfl_xor_sync(0xffffffffu, s0, off);
                s1 += __shfl_xor_sync(0xffffffffu, s1, off);
            }
            if (lane < 4) {
                g_partial[(g0 + rg) * HID + c0]     = s0;
                g_partial[(g0 + rg) * HID + c0 + 1] = s1;
            }
        }
    }
}

// ============================================================
// f-MLP + log_softmax, with fused i-reduction (transposed f weights)
// ============================================================
__global__ void f_kernel(const float* __restrict__ f1b,
                         const float* __restrict__ f2b,
                         const float* __restrict__ f3w, const float* __restrict__ f3b,
                         float* __restrict__ out) {
    int b = blockIdx.x;
    int tid = threadIdx.x;
    __shared__ float h0[HID], h1[HID], h2[HID], lg[NOUT], red[2];

    // fused deterministic reduce over i
    {
        float s = 0.f;
        const float* p = g_partial + b * NOBJ * HID + tid;
        for (int i = 0; i < NOBJ; i++) s += p[i * HID];
        h0[tid] = s;
    }
    __syncthreads();

    {
        float a = f1b[tid];
        const float4* w4 = (const float4*)(g_fT + tid * HID);
        const float4* h4 = (const float4*)h0;
#pragma unroll 8
        for (int k = 0; k < HID / 4; k++) {
            float4 w = w4[k], h = h4[k];
            a += w.x * h.x + w.y * h.y + w.z * h.z + w.w * h.w;
        }
        h1[tid] = fmaxf(a, 0.f);
    }
    __syncthreads();

    {
        float a = f2b[tid];
        const float4* w4 = (const float4*)(g_fT + HID * HID + tid * HID);
        const float4* h4 = (const float4*)h1;
#pragma unroll 8
        for (int k = 0; k < HID / 4; k++) {
            float4 w = w4[k], h = h4[k];
            a += w.x * h.x + w.y * h.y + w.z * h.z + w.w * h.w;
        }
        h2[tid] = fmaxf(a, 0.f);
    }
    __syncthreads();

    if (tid < NOUT) {
        float a = f3b[tid];
        for (int k = 0; k < HID; k++) a += h2[k] * f3w[k * NOUT + tid];
        lg[tid] = a;
    }
    __syncthreads();

    if (tid == 0) {
        float m = lg[0];
        for (int c = 1; c < NOUT; c++) m = fmaxf(m, lg[c]);
        float se = 0.f;
        for (int c = 0; c < NOUT; c++) se += expf(lg[c] - m);
        red[0] = m;
        red[1] = logf(se);
    }
    __syncthreads();

    if (tid < NOUT) out[b * NOUT + tid] = lg[tid] - red[0] - red[1];
}

// ============================================================
extern "C" void kernel_launch(void* const* d_in, const int* in_sizes, int n_in,
                              void* d_out, int out_size) {
    const float* x   = (const float*)d_in[0];
    const float* qst = (const float*)d_in[1];
    const float* g1w = (const float*)d_in[2];
    const float* g1b = (const float*)d_in[3];
    const float* g2w = (const float*)d_in[4];
    const float* g2b = (const float*)d_in[5];
    const float* g3w = (const float*)d_in[6];
    const float* g3b = (const float*)d_in[7];
    const float* g4w = (const float*)d_in[8];
    const float* g4b = (const float*)d_in[9];
    const float* f1w = (const float*)d_in[10];
    const float* f1b = (const float*)d_in[11];
    const float* f2w = (const float*)d_in[12];
    const float* f2b = (const float*)d_in[13];
    const float* f3w = (const float*)d_in[14];
    const float* f3b = (const float*)d_in[15];
    float* out = (float*)d_out;

    cudaFuncSetAttribute(pair_mma_kernel,
                         cudaFuncAttributeMaxDynamicSharedMemorySize, POOL_B);

    prep_kernel<<<NB + 320, 256>>>(x, qst, g1w, g1b, g2w, g3w, g4w, f1w, f2w);
    pair_mma_kernel<<<(NB * NOBJ) / 2, 256, POOL_B>>>(g2b, g3b, g4b);
    f_kernel<<<NB, 256>>>(f1b, f2b, f3w, f3b, out);
}

// round 12
// speedup vs baseline: 1.0359x; 1.0151x over previous
#include <cuda_runtime.h>
#include <cuda_fp16.h>
#include <math.h>
#include <stdint.h>

#define DD    8
#define NOBJ  64
#define KCH   24
#define QDIM  128
#define OBJF  26
#define HID   256
#define NOUT  28
#define NB    64

// ---------------- PTX helpers (arch-agnostic: sm_80+ instructions only) ----
__device__ __forceinline__ uint32_t smem_u32(const void* p) {
    uint32_t r;
    asm("{ .reg .u64 t; cvta.to.shared.u64 t, %1; cvt.u32.u64 %0, t; }"
        : "=r"(r) : "l"(p));
    return r;
}
#define LDSM4(r0, r1, r2, r3, addr) \
    asm volatile("ldmatrix.sync.aligned.m8n8.x4.shared.b16 {%0,%1,%2,%3}, [%4];" \
                 : "=r"(r0), "=r"(r1), "=r"(r2), "=r"(r3) : "r"(addr))
#define MMA16816(c, a0, a1, a2, a3, b0, b1) \
    asm volatile("mma.sync.aligned.m16n8k16.row.col.f32.f16.f16.f32 " \
                 "{%0,%1,%2,%3}, {%4,%5,%6,%7}, {%8,%9}, {%0,%1,%2,%3};" \
                 : "+f"((c)[0]), "+f"((c)[1]), "+f"((c)[2]), "+f"((c)[3]) \
                 : "r"(a0), "r"(a1), "r"(a2), "r"(a3), "r"(b0), "r"(b1))
#define CP_ASYNC16(dst, src) \
    asm volatile("cp.async.cg.shared.global [%0], [%1], 16;" \
                 :: "r"(dst), "l"(src))
#define CP_COMMIT() asm volatile("cp.async.commit_group;" ::: "memory")
#define CP_WAIT1()  asm volatile("cp.async.wait_group 1;" ::: "memory")
#define CP_WAIT0()  asm volatile("cp.async.wait_group 0;" ::: "memory")

// ---------------- SMEM pool layout (dynamic) ----------------
#define H_ROW_B   528
#define H_PLANE_B (128 * H_ROW_B)          // 67584
#define OFF_H     0
#define OFF_W     H_PLANE_B                // 67584
#define W_ROW_B   272
#define W_PLANE_B (256 * W_ROW_B)          // 69632
#define POOL_B    (OFF_W + 2 * W_PLANE_B)  // 206848 (double buffer)

// ---------------- scratch ----------------
__device__ float g_A[NB * NOBJ * HID];
__device__ float g_Bx[NB * NOBJ * HID];
__device__ float g_partial[NB * NOBJ * HID];
__device__ __half g_Wt[3 * HID * HID];     // [layer][n][k]  (B = W^T, k-contig)
__device__ float g_fT[2 * HID * HID];      // f1/f2 weights transposed [c][k]

// ============================================================
// combined prep:
//   blocks 0..255      -> g1 factorization (4 blocks per batch, 16 n-rows each)
//   blocks 256..575    -> coalesced 32x32 tiled transposes of W2/W3/W4/f1/f2
// ============================================================
#define G1_BLOCKS (NB * 4)

__global__ void prep_kernel(const float* __restrict__ x,
                            const float* __restrict__ qst,
                            const float* __restrict__ g1w,
                            const float* __restrict__ g1b,
                            const float* __restrict__ g2w,
                            const float* __restrict__ g3w,
                            const float* __restrict__ g4w,
                            const float* __restrict__ f1w,
                            const float* __restrict__ f2w) {
    int tid = threadIdx.x;
    if (blockIdx.x >= G1_BLOCKS) {
        // ---- tiled transpose: src [k][n] row-major -> dst [n][k] ----
        __shared__ float tile[32][33];
        int tt = blockIdx.x - G1_BLOCKS;   // 0..319
        int l = tt >> 6;                   // 0..4
        int tile_id = tt & 63;
        int tr = tile_id >> 3;             // k-block
        int tc = tile_id & 7;              // n-block
        const float* src = (l == 0) ? g2w : (l == 1) ? g3w : (l == 2) ? g4w
                          : (l == 3) ? f1w : f2w;
        int kb = tr * 32, nb = tc * 32;
        int lr = tid >> 5, lc = tid & 31;  // 8 rows/pass, 32 cols
#pragma unroll
        for (int p = 0; p < 4; p++) {
            int k = kb + lr + p * 8;
            tile[lr + p * 8][lc] = src[k * HID + nb + lc];
        }
        __syncthreads();
        if (l < 3) {
            __half* dst = g_Wt + l * HID * HID;
#pragma unroll
            for (int p = 0; p < 4; p++) {
                int n = nb + lr + p * 8;
                dst[n * HID + kb + lc] = __float2half(tile[lc][lr + p * 8]);
            }
        } else {
            float* dst = g_fT + (l - 3) * HID * HID;
#pragma unroll
            for (int p = 0; p < 4; p++) {
                int n = nb + lr + p * 8;
                dst[n * HID + kb + lc] = tile[lc][lr + p * 8];
            }
        }
        return;
    }

    // ---- g1 factorization: block = (b, quarter); handles n in [q*16, q*16+16)
    int b = blockIdx.x >> 2;
    int nq = blockIdx.x & 3;
    int n0 = nq * 16;

    __shared__ float xf[16][OBJF];
    __shared__ float qs[QDIM];

    // stage this quarter's 16 object rows (x is [b][k][n] with n fastest)
    for (int idx = tid; idx < 16 * KCH; idx += 256) {
        int k = idx / 16, n = idx % 16;
        xf[n][k] = x[(b * KCH + k) * NOBJ + n0 + n];
    }
    if (tid < 16) {
        float a = (float)(n0 + tid);
        xf[tid][24] = (a / 8.0f - 4.0f) / 4.0f;
        xf[tid][25] = (fmodf(a, 8.0f) - 4.0f) / 4.0f;
    }
    if (tid < QDIM) qs[tid] = qst[b * QDIM + tid];
    __syncthreads();

    int c = tid;
    float wa[OBJF], wb[OBJF];
#pragma unroll
    for (int t = 0; t < OBJF; t++) {
        wa[t] = g1w[t * HID + c];
        wb[t] = g1w[(OBJF + t) * HID + c];
    }
    // qst @ Wq with 4 independent accumulators (break the add chain)
    float bq0 = 0.f, bq1 = 0.f, bq2 = 0.f, bq3 = 0.f;
#pragma unroll 8
    for (int q = 0; q < QDIM; q += 4) {
        bq0 += qs[q]     * g1w[(2 * OBJF + q)     * HID + c];
        bq1 += qs[q + 1] * g1w[(2 * OBJF + q + 1) * HID + c];
        bq2 += qs[q + 2] * g1w[(2 * OBJF + q + 2) * HID + c];
        bq3 += qs[q + 3] * g1w[(2 * OBJF + q + 3) * HID + c];
    }
    float bq = g1b[c] + ((bq0 + bq1) + (bq2 + bq3));

#pragma unroll 2
    for (int n = 0; n < 16; n++) {
        float accA = 0.f, accB = bq;
#pragma unroll
        for (int t = 0; t < OBJF; t++) {
            accA += xf[n][t] * wa[t];
            accB += xf[n][t] * wb[t];
        }
        g_A [(b * NOBJ + n0 + n) * HID + c] = accA;
        g_Bx[(b * NOBJ + n0 + n) * HID + c] = accB;
    }
}

// ============================================================
// main tensor kernel (R7 config): 128 pair-rows / CTA, 3 chained layers
// fp16 activations + fp16 W, fp32 accumulate
// 8 warps (256 thr): warp tile 64x64 = 2 row-groups x 4 col-groups
// ============================================================
struct SharedCtl {
    float bx[2 * HID];
    float bias[3 * HID];
};

__device__ __forceinline__ uint32_t pack_h16x2(float a, float b) {
    __half ha = __float2half(a), hb = __float2half(b);
    return (uint32_t)__half_as_ushort(ha) |
           ((uint32_t)__half_as_ushort(hb) << 16);
}

__global__ __launch_bounds__(256, 1)
void pair_mma_kernel(const float* __restrict__ g2b,
                     const float* __restrict__ g3b,
                     const float* __restrict__ g4b) {
    extern __shared__ char pool[];
    __shared__ SharedCtl ctl;

    int tid = threadIdx.x;
    int wid = tid >> 5;
    int lane = tid & 31;
    int g0 = blockIdx.x * 2;           // pair index (b*64+i), even
    int b = g0 >> 6;

    int rg = wid >> 2;                 // row group: rows rg*64 .. +63  (== half)
    int cg = wid & 3;                  // col group: cols cg*64 .. +63
    int row0 = rg * 64;
    int col0 = cg * 64;

    uint32_t pool_u = smem_u32(pool);
    uint32_t H_u = pool_u + OFF_H;
    uint32_t W_u = pool_u + OFF_W;

    // stage biases + Bx rows
    ctl.bias[tid]           = g2b[tid];
    ctl.bias[HID + tid]     = g3b[tid];
    ctl.bias[2 * HID + tid] = g4b[tid];
    ctl.bx[tid]       = g_Bx[g0 * HID + tid];
    ctl.bx[HID + tid] = g_Bx[(g0 + 1) * HID + tid];

    // prefetch W slab 0 (layer 0, k=0..127) while we build H1
    {
#pragma unroll
        for (int it = 0; it < 16; it++) {
            int e = tid + it * 256;            // 0..4095: n, kq
            int n = e >> 4, kq = e & 15;
            const __half* src = g_Wt + n * HID + kq * 8;
            uint32_t dst = W_u + n * W_ROW_B + kq * 16;
            CP_ASYNC16(dst, src);
        }
        CP_COMMIT();
    }
    __syncthreads();   // ctl.bx visible

    // ---- H1 = relu(gA[j] + bx[half]) -> fp16 plane ----
    {
        const float* Ag = g_A + b * NOBJ * HID;
#pragma unroll
        for (int it = 0; it < 64; it++) {
            int idx = tid + it * 256;          // 0..16383 -> (row, colpair)
            int row = idx >> 7;
            int cp = (idx & 127) * 2;
            int j = row & 63, hf = row >> 6;
            float2 av = *(const float2*)(Ag + j * HID + cp);
            float v0 = fmaxf(av.x + ctl.bx[hf * HID + cp], 0.f);
            float v1 = fmaxf(av.y + ctl.bx[hf * HID + cp + 1], 0.f);
            uint32_t off = (uint32_t)(row * H_ROW_B + cp * 2);
            *(uint32_t*)(pool + OFF_H + off) = pack_h16x2(v0, v1);
        }
    }

    float acc[32][4];   // [at*8 + b8][quad]  (at: 4 m16 tiles, b8: 8 n8 tiles)

    // ---- 6 slab iterations: 3 layers x 2 k-slabs (k=128 each) ----
    for (int t = 0; t < 6; t++) {
        int l = t >> 1, s = t & 1;
        if (s == 0) {
#pragma unroll
            for (int u = 0; u < 32; u++)
#pragma unroll
                for (int q = 0; q < 4; q++) acc[u][q] = 0.f;
        }

        // prefetch next slab into the other buffer
        if (t + 1 < 6) {
            int nl = (t + 1) >> 1, ns = (t + 1) & 1;
            uint32_t wbuf = W_u + ((t + 1) & 1) * W_PLANE_B;
#pragma unroll
            for (int it = 0; it < 16; it++) {
                int e = tid + it * 256;
                int n = e >> 4, kq = e & 15;
                const __half* src = g_Wt + nl * HID * HID + n * HID + ns * 128 + kq * 8;
                uint32_t dst = wbuf + n * W_ROW_B + kq * 16;
                CP_ASYNC16(dst, src);
            }
            CP_COMMIT();
            CP_WAIT1();
        } else {
            CP_WAIT0();
        }
        __syncthreads();   // current slab ready; prev compute done; H writes visible

        // ---- compute slab (k=128: 8 k16 steps) ----
        uint32_t wsl = W_u + (t & 1) * W_PLANE_B;
#pragma unroll
        for (int kst = 0; kst < 8; kst++) {
            int kglob = s * 128 + kst * 16;
            // A fragments: 4 m16 tiles of this warp's 64 rows
            uint32_t ah[4][4];
#pragma unroll
            for (int at = 0; at < 4; at++) {
                uint32_t a_off = (uint32_t)((row0 + at * 16 + (lane & 15)) * H_ROW_B +
                                            kglob * 2 + (lane >> 4) * 16);
                LDSM4(ah[at][0], ah[at][1], ah[at][2], ah[at][3], H_u + a_off);
            }
            uint32_t b_off = (uint32_t)((lane & 15) * W_ROW_B + kst * 32 +
                                        (lane >> 4) * 16);
            // B fragments: 4 n16 tiles of this warp's 64 cols
#pragma unroll
            for (int bt = 0; bt < 4; bt++) {
                uint32_t bh[4];
                uint32_t bb = wsl + (uint32_t)((col0 + bt * 16) * W_ROW_B) + b_off;
                LDSM4(bh[0], bh[1], bh[2], bh[3], bb);
#pragma unroll
                for (int at = 0; at < 4; at++) {
                    float* a0 = acc[at * 8 + 2 * bt];
                    float* a1 = acc[at * 8 + 2 * bt + 1];
                    MMA16816(a0, ah[at][0], ah[at][1], ah[at][2], ah[at][3], bh[0], bh[2]);
                    MMA16816(a1, ah[at][0], ah[at][1], ah[at][2], ah[at][3], bh[1], bh[3]);
                }
            }
        }
        __syncthreads();   // all warps done reading H / this W buffer

        // ---- layer epilogue (layers 0,1): bias+relu -> fp16 H plane ----
        if (s == 1 && l < 2) {
#pragma unroll
            for (int at = 0; at < 4; at++) {
                int r0 = row0 + at * 16 + (lane >> 2);
                int r1 = r0 + 8;
#pragma unroll
                for (int b8 = 0; b8 < 8; b8++) {
                    float* a = acc[at * 8 + b8];
                    int c0 = col0 + b8 * 8 + (lane & 3) * 2;
                    float2 bias2 = *(const float2*)&ctl.bias[l * HID + c0];
                    float v00 = fmaxf(a[0] + bias2.x, 0.f);
                    float v01 = fmaxf(a[1] + bias2.y, 0.f);
                    float v10 = fmaxf(a[2] + bias2.x, 0.f);
                    float v11 = fmaxf(a[3] + bias2.y, 0.f);
                    uint32_t off0 = (uint32_t)(r0 * H_ROW_B + c0 * 2);
                    uint32_t off1 = (uint32_t)(r1 * H_ROW_B + c0 * 2);
                    *(uint32_t*)(pool + OFF_H + off0) = pack_h16x2(v00, v01);
                    *(uint32_t*)(pool + OFF_H + off1) = pack_h16x2(v10, v11);
                }
            }
        }
    }

    // ---- final layer: bias+relu, reduce this warp's 64 rows (one half),
    //      64 private cols -> direct store to g_partial
    {
#pragma unroll
        for (int b8 = 0; b8 < 8; b8++) {
            int c0 = col0 + b8 * 8 + (lane & 3) * 2;
            float2 bias2 = *(const float2*)&ctl.bias[2 * HID + c0];
            float s0 = 0.f, s1 = 0.f;
#pragma unroll
            for (int at = 0; at < 4; at++) {
                float* a = acc[at * 8 + b8];
                s0 += fmaxf(a[0] + bias2.x, 0.f) + fmaxf(a[2] + bias2.x, 0.f);
                s1 += fmaxf(a[1] + bias2.y, 0.f) + fmaxf(a[3] + bias2.y, 0.f);
            }
#pragma unroll
            for (int off = 4; off < 32; off <<= 1) {
                s0 += __shfl_xor_sync(0xffffffffu, s0, off);
                s1 += __shfl_xor_sync(0xffffffffu, s1, off);
            }
            if (lane < 4) {
                g_partial[(g0 + rg) * HID + c0]     = s0;
                g_partial[(g0 + rg) * HID + c0 + 1] = s1;
            }
        }
    }
}

// ============================================================
// f-MLP + log_softmax, with fused i-reduction (transposed f weights)
// ============================================================
__global__ void f_kernel(const float* __restrict__ f1b,
                         const float* __restrict__ f2b,
                         const float* __restrict__ f3w, const float* __restrict__ f3b,
                         float* __restrict__ out) {
    int b = blockIdx.x;
    int tid = threadIdx.x;
    __shared__ float h0[HID], h1[HID], h2[HID], lg[NOUT], red[2];

    // fused deterministic reduce over i
    {
        float s = 0.f;
        const float* p = g_partial + b * NOBJ * HID + tid;
        for (int i = 0; i < NOBJ; i++) s += p[i * HID];
        h0[tid] = s;
    }
    __syncthreads();

    {
        float a = f1b[tid];
        const float4* w4 = (const float4*)(g_fT + tid * HID);
        const float4* h4 = (const float4*)h0;
#pragma unroll 8
        for (int k = 0; k < HID / 4; k++) {
            float4 w = w4[k], h = h4[k];
            a += w.x * h.x + w.y * h.y + w.z * h.z + w.w * h.w;
        }
        h1[tid] = fmaxf(a, 0.f);
    }
    __syncthreads();

    {
        float a = f2b[tid];
        const float4* w4 = (const float4*)(g_fT + HID * HID + tid * HID);
        const float4* h4 = (const float4*)h1;
#pragma unroll 8
        for (int k = 0; k < HID / 4; k++) {
            float4 w = w4[k], h = h4[k];
            a += w.x * h.x + w.y * h.y + w.z * h.z + w.w * h.w;
        }
        h2[tid] = fmaxf(a, 0.f);
    }
    __syncthreads();

    if (tid < NOUT) {
        float a = f3b[tid];
        for (int k = 0; k < HID; k++) a += h2[k] * f3w[k * NOUT + tid];
        lg[tid] = a;
    }
    __syncthreads();

    if (tid == 0) {
        float m = lg[0];
        for (int c = 1; c < NOUT; c++) m = fmaxf(m, lg[c]);
        float se = 0.f;
        for (int c = 0; c < NOUT; c++) se += expf(lg[c] - m);
        red[0] = m;
        red[1] = logf(se);
    }
    __syncthreads();

    if (tid < NOUT) out[b * NOUT + tid] = lg[tid] - red[0] - red[1];
}

// ============================================================
extern "C" void kernel_launch(void* const* d_in, const int* in_sizes, int n_in,
                              void* d_out, int out_size) {
    const float* x   = (const float*)d_in[0];
    const float* qst = (const float*)d_in[1];
    const float* g1w = (const float*)d_in[2];
    const float* g1b = (const float*)d_in[3];
    const float* g2w = (const float*)d_in[4];
    const float* g2b = (const float*)d_in[5];
    const float* g3w = (const float*)d_in[6];
    const float* g3b = (const float*)d_in[7];
    const float* g4w = (const float*)d_in[8];
    const float* g4b = (const float*)d_in[9];
    const float* f1w = (const float*)d_in[10];
    const float* f1b = (const float*)d_in[11];
    const float* f2w = (const float*)d_in[12];
    const float* f2b = (const float*)d_in[13];
    const float* f3w = (const float*)d_in[14];
    const float* f3b = (const float*)d_in[15];
    float* out = (float*)d_out;

    cudaFuncSetAttribute(pair_mma_kernel,
                         cudaFuncAttributeMaxDynamicSharedMemorySize, POOL_B);

    prep_kernel<<<G1_BLOCKS + 320, 256>>>(x, qst, g1w, g1b, g2w, g3w, g4w, f1w, f2w);
    pair_mma_kernel<<<(NB * NOBJ) / 2, 256, POOL_B>>>(g2b, g3b, g4b);
    f_kernel<<<NB, 256>>>(f1b, f2b, f3w, f3b, out);
}